// round 7
// baseline (speedup 1.0000x reference)
#include <cuda_runtime.h>
#include <cstdint>

// Shapes (fixed by the problem)
#define N_SAMP 32768
#define D_DIM  256
#define M_ST   4
#define K_CODE 1024

// Output layout (element offsets into f32 d_out)
#define OFF_XQ   0
#define OFF_LOSS 8388608
#define OFF_IDX  8388609
#define OFF_EMB  8519681
#define OFF_AVG  9568257
#define OFF_CS   10616833
#define OUT_TOT  10620929

// Scratch (device global — no allocation allowed)
__device__ __align__(16) float g_part[256 * 256];   // per-block column partials of x

// ---- TMA bulk-store helpers (1D shared::cta -> global) ----------------------
__device__ __forceinline__ void bulk_store_1d(void* gdst, uint32_t ssrc, uint32_t nbytes) {
    asm volatile("cp.async.bulk.global.shared::cta.bulk_group [%0], [%1], %2;"
                 :: "l"(gdst), "r"(ssrc), "r"(nbytes) : "memory");
}
__device__ __forceinline__ void bulk_commit() {
    asm volatile("cp.async.bulk.commit_group;" ::: "memory");
}
__device__ __forceinline__ void bulk_wait0() {
    asm volatile("cp.async.bulk.wait_group 0;" ::: "memory");
}
__device__ __forceinline__ void fence_async_shared() {
    asm volatile("fence.proxy.async.shared::cta;" ::: "memory");
}

// ---------------------------------------------------------------------------
// K1: colsum + cs + emb/avg(k!=0) + zero-region bulk stores.  blockDim = 256.
//   [0,256)    colsum partials of x (float4) -> g_part   (reads overlap writes)
//   [256,260)  cluster_size outputs
//   [260,772)  emb/avg outputs for k != 0 (scalar, byte-misaligned region)
//   [772,776)  zero-fill loss+indices via TMA bulk (128KB each) + tail scalar
// ---------------------------------------------------------------------------
__global__ void __launch_bounds__(256) k1_main(
        const float* __restrict__ x,
        const float* __restrict__ emb,
        const float* __restrict__ avg,
        const float* __restrict__ cs_in,
        float* __restrict__ out, int out_size) {
    __shared__ __align__(16) float sbuf[4096];       // 16KB, reused per branch
    const int b = blockIdx.x;
    const int tid = threadIdx.x;

    if (b < 256) {
        // ---- colsum partial: block b covers rows [b*128, b*128+128).
        const int r_off = tid >> 6;
        const int c4 = tid & 63;
        const float4* x4 = (const float4*)x;
        float4 acc = make_float4(0.f, 0.f, 0.f, 0.f);
        const long base = (long)b * 128 * 64 + c4;
#pragma unroll 8
        for (int r = r_off; r < 128; r += 4) {
            float4 v = x4[base + (long)r * 64];
            acc.x += v.x; acc.y += v.y; acc.z += v.z; acc.w += v.w;
        }
        float4* s4 = (float4*)sbuf;
        s4[tid] = acc;
        __syncthreads();
        if (tid < 64) {
            float4 a = s4[tid], b1 = s4[tid + 64], c = s4[tid + 128], d = s4[tid + 192];
            float4 r;
            r.x = ((a.x + b1.x) + c.x) + d.x;
            r.y = ((a.y + b1.y) + c.y) + d.y;
            r.z = ((a.z + b1.z) + c.z) + d.z;
            r.w = ((a.w + b1.w) + c.w) + d.w;
            ((float4*)g_part)[b * 64 + tid] = r;
        }
    } else if (b < 260) {
        // ---- cluster_size outputs for stage i
        const int i = b - 256;
#pragma unroll
        for (int j = 0; j < 4; ++j) {
            const int k = tid + j * 256;
            const float c = cs_in[i * K_CODE + k] * 0.99f +
                            ((k == 0) ? 327.68f : 0.f);
            const int o = OFF_CS + i * K_CODE + k;
            if (o < out_size) out[o] = c;
        }
    } else if (b < 772) {
        // ---- emb/avg for k != 0. blk in [0,512): 128 blocks/stage, 8 rows each.
        const int blk = b - 260;
        const int i = blk >> 7;                          // stage
        const int r0 = (blk & 127) * 8;                  // first k of this block
        {
            const float* csr = cs_in + i * K_CODE;
            float s = ((csr[tid] + csr[tid + 256]) + csr[tid + 512]) + csr[tid + 768];
            sbuf[tid] = s;
            __syncthreads();
            for (int st = 128; st > 0; st >>= 1) {
                if (tid < st) sbuf[tid] += sbuf[tid + st];
                __syncthreads();
            }
        }
        const float n = 0.99f * sbuf[0] + 327.68f;
        const float denom = n + 1024.0f * 1e-5f;
#pragma unroll
        for (int r = 0; r < 8; ++r) {
            const int k = r0 + r;
            if (k == 0) continue;                        // handled by K2
            const int row = i * K_CODE + k;
            const float c = cs_in[row] * 0.99f;
            const float w = (c + 1e-5f) / denom * n;
            const float iw = 1.0f / w;
            const int t = row * D_DIM + tid;
            const float na = 0.99f * avg[t];             // sum_term == 0 for k != 0
            const int oa = OFF_AVG + t;
            const int oe = OFF_EMB + t;
            if (oa < out_size) out[oa] = na;
            if (oe < out_size) out[oe] = na * iw;
        }
    } else {
        // ---- zero-fill loss + indices via bulk stores.
        // Region bytes [33554432, 33554432 + 524288), 4 blocks x 8 x 16KB.
        const int z = b - 772;
        float4* s4 = (float4*)sbuf;
#pragma unroll
        for (int j = 0; j < 4; ++j)
            s4[tid + j * 256] = make_float4(0.f, 0.f, 0.f, 0.f);
        __syncthreads();
        fence_async_shared();
        if (tid == 0) {
            const uint32_t saddr = (uint32_t)__cvta_generic_to_shared(sbuf);
            const long out_bytes = (long)out_size * 4;
#pragma unroll
            for (int j = 0; j < 8; ++j) {
                const long dst = 33554432L + (long)z * 131072 + (long)j * 16384;
                if (dst + 16384 <= out_bytes)
                    bulk_store_1d((char*)out + dst, saddr, 16384);
            }
            bulk_commit();
            bulk_wait0();
        }
        if (z == 0 && tid == 1 && 8519680 < out_size) out[8519680] = 0.f;
    }
}

// ---------------------------------------------------------------------------
// K2: row0 (needs g_part from K1) + x_q bulk stores.  blockDim = 256.
//   [0,4)      k==0 rows of each stage
//   [4,260)    x_q: fill 16KB SMEM with the 1KB s-pattern, 8 x 16KB bulk stores
// ---------------------------------------------------------------------------
__global__ void __launch_bounds__(256) k2_xq_row0(
        const float* __restrict__ emb,
        const float* __restrict__ avg,
        const float* __restrict__ cs_in,
        float* __restrict__ out, int out_size) {
    __shared__ __align__(16) float sbuf[4096];       // 16KB
    const int b = blockIdx.x;
    const int tid = threadIdx.x;

    if (b < 4) {
        // ---- k==0 row of stage i. d = tid.
        const int i = b;
        {
            const float* csr = cs_in + i * K_CODE;
            float s = ((csr[tid] + csr[tid + 256]) + csr[tid + 512]) + csr[tid + 768];
            sbuf[tid] = s;
            __syncthreads();
            for (int st = 128; st > 0; st >>= 1) {
                if (tid < st) sbuf[tid] += sbuf[tid + st];
                __syncthreads();
            }
        }
        const float n = 0.99f * sbuf[0] + 327.68f;

        // Sx[d] = fixed-order sum of 256 partials (L2-hot, high MLP)
        const int d = tid;
        float sx = 0.f;
#pragma unroll 16
        for (int p = 0; p < 256; ++p)
            sx += g_part[p * D_DIM + d];

        float pi = 0.f;
        for (int j = 0; j < i; ++j) pi += emb[(size_t)j * K_CODE * D_DIM + d];
        const float sum_term = sx - 32768.0f * pi;
        const int t = i * K_CODE * D_DIM + d;            // (i, 0, d)
        const float na = 0.99f * avg[t] + 0.01f * sum_term;
        const float c0 = cs_in[i * K_CODE] * 0.99f + 327.68f;
        const float w = (c0 + 1e-5f) / (n + 1024.0f * 1e-5f) * n;
        const int oa = OFF_AVG + t;
        const int oe = OFF_EMB + t;
        if (oa < out_size) out[oa] = na;
        if (oe < out_size) out[oe] = na / w;
    } else {
        // ---- x_q bulk: block handles bytes [blk*131072, blk*131072 + 131072).
        const int blk = b - 4;                           // [0, 256)
        // s[d] = sum over stages of emb[i, 0, d]  (same order as prior rounds)
        const float s_d = ((emb[tid] + emb[262144 + tid]) + emb[524288 + tid])
                          + emb[786432 + tid];
#pragma unroll
        for (int r = 0; r < 16; ++r)
            sbuf[r * 256 + tid] = s_d;
        __syncthreads();
        fence_async_shared();
        if (tid == 0) {
            const uint32_t saddr = (uint32_t)__cvta_generic_to_shared(sbuf);
            const long out_bytes = (long)out_size * 4;
#pragma unroll
            for (int j = 0; j < 8; ++j) {
                const long dst = (long)blk * 131072 + (long)j * 16384;
                if (dst + 16384 <= out_bytes)
                    bulk_store_1d((char*)out + dst, saddr, 16384);
            }
            bulk_commit();
            bulk_wait0();
        }
    }
}

extern "C" void kernel_launch(void* const* d_in, const int* in_sizes, int n_in,
                              void* d_out, int out_size) {
    const float* x   = (const float*)d_in[0];  // [N, D]
    const float* emb = (const float*)d_in[1];  // [M, K, D]
    const float* avg = (const float*)d_in[2];  // [M, K, D]
    const float* cs  = (const float*)d_in[3];  // [M, K]
    float* out = (float*)d_out;

    k1_main<<<776, 256>>>(x, emb, avg, cs, out, out_size);
    k2_xq_row0<<<260, 256>>>(emb, avg, cs, out, out_size);
}